// round 7
// baseline (speedup 1.0000x reference)
#include <cuda_runtime.h>
#include <cuda_bf16.h>
#include <cstdint>
#include <cstddef>

// Problem constants
#define NN   50000
#define EE   200000
#define RR   4
#define DIN  128
#define DH   128
#define DOUT 64

#define SCAN_N (RR * NN)
#define CHUNK  2048
#define NBLK   ((SCAN_N + CHUNK - 1) / CHUNK)   // 98

// smem row stride for MMA tiles: 128 bf16 + 8 pad = 272 bytes (bank-rotating)
#define ROWB 272

// -------- scratch (static device globals) --------
__device__ float g_Wh1[RR * NN * DH];
__device__ float g_Wh2[RR * NN * DOUT];
__device__ __nv_bfloat16 g_featH[NN * DIN];
__device__ __nv_bfloat16 g_featL[NN * DIN];
__device__ __nv_bfloat16 g_hH[NN * DH];
__device__ __nv_bfloat16 g_hL[NN * DH];
__device__ __nv_bfloat16 g_w1H[RR * DH * DIN];    // [r][n][k]
__device__ __nv_bfloat16 g_w1L[RR * DH * DIN];
__device__ __nv_bfloat16 g_w2H[RR * DOUT * DH];   // [r][n][k]
__device__ __nv_bfloat16 g_w2L[RR * DOUT * DH];
__device__ int g_deg[SCAN_N];
__device__ int g_off[SCAN_N];
__device__ int g_cur[SCAN_N];
__device__ int g_bsum[NBLK];
__device__ int g_esrc[RR * EE];

__device__ __forceinline__ uint32_t smem_to_u32(const void* p) {
    uint32_t a;
    asm("{ .reg .u64 t; cvta.to.shared.u64 t, %1; cvt.u32.u64 %0, t; }"
        : "=r"(a) : "l"(p));
    return a;
}

#define LDSM_X4(r0, r1, r2, r3, addr) \
    asm volatile("ldmatrix.sync.aligned.m8n8.x4.shared.b16 {%0,%1,%2,%3}, [%4];" \
                 : "=r"(r0), "=r"(r1), "=r"(r2), "=r"(r3) : "r"(addr))

#define MMA_BF16(c, a, b0, b1) \
    asm volatile("mma.sync.aligned.m16n8k16.row.col.f32.bf16.bf16.f32 " \
                 "{%0,%1,%2,%3},{%4,%5,%6,%7},{%8,%9},{%0,%1,%2,%3};" \
                 : "+f"((c)[0]), "+f"((c)[1]), "+f"((c)[2]), "+f"((c)[3]) \
                 : "r"((a)[0]), "r"((a)[1]), "r"((a)[2]), "r"((a)[3]), \
                   "r"(b0), "r"(b1))

// -------- precision split --------
__device__ __forceinline__ void split_bf16(float v, __nv_bfloat16& h, __nv_bfloat16& l) {
    h = __float2bfloat16(v);
    l = __float2bfloat16(v - __bfloat162float(h));
}

// ==================== prep kernels ====================
__global__ void k_cvt_feat(const float* __restrict__ x) {
    int i = blockIdx.x * 256 + threadIdx.x;          // float4 index
    if (i >= NN * DIN / 4) return;
    float4 v = reinterpret_cast<const float4*>(x)[i];
    __nv_bfloat16 h0, l0, h1, l1, h2, l2, h3, l3;
    split_bf16(v.x, h0, l0); split_bf16(v.y, h1, l1);
    split_bf16(v.z, h2, l2); split_bf16(v.w, h3, l3);
    __nv_bfloat162 H0; H0.x = h0; H0.y = h1;
    __nv_bfloat162 H1; H1.x = h2; H1.y = h3;
    __nv_bfloat162 L0; L0.x = l0; L0.y = l1;
    __nv_bfloat162 L1; L1.x = l2; L1.y = l3;
    reinterpret_cast<__nv_bfloat162*>(g_featH)[2 * i]     = H0;
    reinterpret_cast<__nv_bfloat162*>(g_featH)[2 * i + 1] = H1;
    reinterpret_cast<__nv_bfloat162*>(g_featL)[2 * i]     = L0;
    reinterpret_cast<__nv_bfloat162*>(g_featL)[2 * i + 1] = L1;
}

__global__ void k_prep_w1(const float* __restrict__ W) {
    int i = blockIdx.x * 256 + threadIdx.x;
    if (i >= RR * 128 * 128) return;
    int r = i >> 14, kn = i & 16383, k = kn >> 7, n = kn & 127;
    float w = W[i];
    __nv_bfloat16 h, l; split_bf16(w, h, l);
    int o = r * 16384 + n * 128 + k;
    g_w1H[o] = h; g_w1L[o] = l;
}
__global__ void k_prep_w2(const float* __restrict__ W) {
    int i = blockIdx.x * 256 + threadIdx.x;
    if (i >= RR * 128 * 64) return;
    int r = i / (128 * 64), kn = i % (128 * 64), k = kn >> 6, n = kn & 63;
    float w = W[i];
    __nv_bfloat16 h, l; split_bf16(w, h, l);
    int o = r * 64 * 128 + n * 128 + k;
    g_w2H[o] = h; g_w2L[o] = l;
}

// ==================== degree / CSR build ====================
__global__ void k_zero() {
    int i = blockIdx.x * 256 + threadIdx.x;
    if (i < SCAN_N) { g_deg[i] = 0; g_cur[i] = 0; }
}
__global__ void k_count(const int* __restrict__ edges) {
    int i = blockIdx.x * 256 + threadIdx.x;
    if (i >= RR * EE) return;
    int r = i / EE, e = i - r * EE;
    int dst = edges[r * 2 * EE + EE + e];
    atomicAdd(&g_deg[r * NN + dst], 1);
}
__global__ __launch_bounds__(256) void k_scan1() {
    __shared__ int wsum[8];
    const int b = blockIdx.x, t = threadIdx.x;
    const int base = b * CHUNK + t * 8;
    int v[8]; int s = 0;
#pragma unroll
    for (int i = 0; i < 8; ++i) {
        int idx = base + i;
        int x = (idx < SCAN_N) ? g_deg[idx] : 0;
        v[i] = s; s += x;
    }
    const int lane = t & 31, w = t >> 5;
    int x = s;
#pragma unroll
    for (int o = 1; o < 32; o <<= 1) {
        int n = __shfl_up_sync(~0u, x, o);
        if (lane >= o) x += n;
    }
    if (lane == 31) wsum[w] = x;
    __syncthreads();
    if (t == 0) {
        int acc = 0;
#pragma unroll
        for (int i = 0; i < 8; ++i) { int tmp = wsum[i]; wsum[i] = acc; acc += tmp; }
        g_bsum[b] = acc;
    }
    __syncthreads();
    const int toff = wsum[w] + (x - s);
#pragma unroll
    for (int i = 0; i < 8; ++i) {
        int idx = base + i;
        if (idx < SCAN_N) g_off[idx] = toff + v[i];
    }
}
__global__ void k_scan2() {
    __shared__ int ws[4];
    const int t = threadIdx.x;
    const int v = (t < NBLK) ? g_bsum[t] : 0;
    const int lane = t & 31, w = t >> 5;
    int x = v;
#pragma unroll
    for (int o = 1; o < 32; o <<= 1) {
        int n = __shfl_up_sync(~0u, x, o);
        if (lane >= o) x += n;
    }
    if (lane == 31) ws[w] = x;
    __syncthreads();
    if (t == 0) {
        int acc = 0;
#pragma unroll
        for (int i = 0; i < 4; ++i) { int tmp = ws[i]; ws[i] = acc; acc += tmp; }
    }
    __syncthreads();
    if (t < NBLK) g_bsum[t] = (x - v) + ws[w];
}
__global__ void k_scan3() {
    int i = blockIdx.x * 256 + threadIdx.x;
    if (i < SCAN_N) g_off[i] += g_bsum[i >> 11];
}
__global__ void k_bin(const int* __restrict__ edges) {
    int i = blockIdx.x * 256 + threadIdx.x;
    if (i >= RR * EE) return;
    int r = i / EE, e = i - r * EE;
    const int* eb = edges + r * 2 * EE;
    int src = eb[e];
    int dst = eb[EE + e];
    int idx = r * NN + dst;
    int pos = g_off[idx] + atomicAdd(&g_cur[idx], 1);
    g_esrc[pos] = src;
}

// ==================== bf16x3 GEMM via mma.sync ====================
// C[r] = A @ W_r^T. CTA: 256 thr = 8 warps, tile 64m x NB n, K=128 resident.
// Warp grid 2m x 4n: warp = 32m x NB/4 n; NT = NB/64 jt-steps of 16 cols.
template <int ROWS>
__device__ __forceinline__ void load_tile(char* dst, const __nv_bfloat16* __restrict__ src,
                                          int valid_rows, int tid) {
#pragma unroll
    for (int i = 0; i < ROWS * 16 / 256; ++i) {
        const int j = i * 256 + tid;
        const int row = j >> 4;
        const int c16 = j & 15;
        uint4 v = make_uint4(0u, 0u, 0u, 0u);
        if (row < valid_rows)
            v = *reinterpret_cast<const uint4*>(src + (size_t)row * 128 + c16 * 8);
        *reinterpret_cast<uint4*>(dst + row * ROWB + c16 * 16) = v;
    }
}

template <int NB>   // 128 (layer1) or 64 (layer2)
__global__ __launch_bounds__(256, 2)
void k_mma(const __nv_bfloat16* __restrict__ AH, const __nv_bfloat16* __restrict__ AL,
           const __nv_bfloat16* __restrict__ BH, const __nv_bfloat16* __restrict__ BL,
           float* __restrict__ C)
{
    constexpr int NT = NB / 64;     // 16-col jt steps per warp (warp n = NB/4)
    extern __shared__ __align__(16) char smem[];
    char* sAh = smem;
    char* sAl = sAh + 64 * ROWB;
    char* sBh = sAl + 64 * ROWB;
    char* sBl = sBh + NB * ROWB;

    const int tid  = threadIdx.x;
    const int lane = tid & 31;
    const int wid  = tid >> 5;
    const int m0   = blockIdx.x * 64;
    const int r    = blockIdx.y;
    const int valid = NN - m0;

    load_tile<64>(sAh, AH + (size_t)m0 * 128, valid < 64 ? valid : 64, tid);
    load_tile<64>(sAl, AL + (size_t)m0 * 128, valid < 64 ? valid : 64, tid);
    load_tile<NB>(sBh, BH + (size_t)r * NB * 128, NB, tid);
    load_tile<NB>(sBl, BL + (size_t)r * NB * 128, NB, tid);
    __syncthreads();

    const int wm = (wid >> 2) * 32;          // warp m offset (2 groups)
    const int wn = (wid & 3) * (NB / 4);     // warp n offset (4 groups)

    // lane-dependent ldmatrix address components (bytes)
    const int aoff = (lane & 15) * ROWB + (lane >> 4) * 16;
    const int boff = ((lane & 7) + ((lane >> 4) << 3)) * ROWB + ((lane >> 3) & 1) * 16;

    const uint32_t uAh = smem_to_u32(sAh);
    const uint32_t uAl = smem_to_u32(sAl);
    const uint32_t uBh = smem_to_u32(sBh);
    const uint32_t uBl = smem_to_u32(sBl);

    float acc[2][NT * 2][4];
#pragma unroll
    for (int mt = 0; mt < 2; ++mt)
#pragma unroll
        for (int nt = 0; nt < NT * 2; ++nt)
#pragma unroll
            for (int q = 0; q < 4; ++q) acc[mt][nt][q] = 0.f;

#pragma unroll
    for (int ks = 0; ks < 8; ++ks) {
        const int kb = ks * 32;              // k16 step in bytes (16 bf16)
        uint32_t ah[2][4], al[2][4];
#pragma unroll
        for (int mt = 0; mt < 2; ++mt) {
            const uint32_t base = (wm + mt * 16) * ROWB + aoff + kb;
            LDSM_X4(ah[mt][0], ah[mt][1], ah[mt][2], ah[mt][3], uAh + base);
            LDSM_X4(al[mt][0], al[mt][1], al[mt][2], al[mt][3], uAl + base);
        }
#pragma unroll
        for (int jt = 0; jt < NT; ++jt) {    // pair of n8 tiles per iter
            const uint32_t bbase = (wn + jt * 16) * ROWB + boff + kb;
            uint32_t bh[4], bl[4];
            LDSM_X4(bh[0], bh[1], bh[2], bh[3], uBh + bbase);
            LDSM_X4(bl[0], bl[1], bl[2], bl[3], uBl + bbase);
#pragma unroll
            for (int mt = 0; mt < 2; ++mt) {
                MMA_BF16(acc[mt][2 * jt],     ah[mt], bh[0], bh[1]);
                MMA_BF16(acc[mt][2 * jt + 1], ah[mt], bh[2], bh[3]);
                MMA_BF16(acc[mt][2 * jt],     ah[mt], bl[0], bl[1]);
                MMA_BF16(acc[mt][2 * jt + 1], ah[mt], bl[2], bl[3]);
                MMA_BF16(acc[mt][2 * jt],     al[mt], bh[0], bh[1]);
                MMA_BF16(acc[mt][2 * jt + 1], al[mt], bh[2], bh[3]);
            }
        }
    }

    // epilogue: m16n8 frag: c0,c1 -> (row lane>>2, col (lane&3)*2), c2,c3 -> row+8
    float* Cr = C + (size_t)r * NN * NB;
#pragma unroll
    for (int mt = 0; mt < 2; ++mt) {
        const int row0 = m0 + wm + mt * 16 + (lane >> 2);
#pragma unroll
        for (int nt = 0; nt < NT * 2; ++nt) {
            const int col = wn + nt * 8 + (lane & 3) * 2;
            if (row0 < NN)
                *reinterpret_cast<float2*>(Cr + (size_t)row0 * NB + col) =
                    make_float2(acc[mt][nt][0], acc[mt][nt][1]);
            if (row0 + 8 < NN)
                *reinterpret_cast<float2*>(Cr + (size_t)(row0 + 8) * NB + col) =
                    make_float2(acc[mt][nt][2], acc[mt][nt][3]);
        }
    }
}

// ==================== CSR gather-sum aggregators ====================
__global__ __launch_bounds__(256)
void k_agg1(const float* __restrict__ b1) {
    const int gw = (blockIdx.x * 256 + threadIdx.x) >> 5;
    if (gw >= NN) return;
    const int lane = threadIdx.x & 31;
    float4 acc = make_float4(0.f, 0.f, 0.f, 0.f);
#pragma unroll
    for (int r = 0; r < RR; ++r) {
        const int idx = r * NN + gw;
        const int deg = g_deg[idx];
        if (deg == 0) continue;
        const int beg = g_off[idx];
        float4 s = make_float4(0.f, 0.f, 0.f, 0.f);
        for (int bse = 0; bse < deg; bse += 32) {
            const int my = bse + lane;
            const int src_l = (my < deg) ? g_esrc[beg + my] : 0;
            const int n = min(32, deg - bse);
            for (int j = 0; j < n; ++j) {
                const int src = __shfl_sync(~0u, src_l, j);
                const float4 v = *reinterpret_cast<const float4*>(
                    g_Wh1 + ((size_t)r * NN + src) * DH + lane * 4);
                s.x += v.x; s.y += v.y; s.z += v.z; s.w += v.w;
            }
        }
        const float d = 1.0f / (float)deg;
        const float4 bb = *reinterpret_cast<const float4*>(b1 + r * DH + lane * 4);
        acc.x += s.x * d + bb.x;
        acc.y += s.y * d + bb.y;
        acc.z += s.z * d + bb.z;
        acc.w += s.w * d + bb.w;
    }
    acc.x = fmaxf(acc.x, 0.f);
    acc.y = fmaxf(acc.y, 0.f);
    acc.z = fmaxf(acc.z, 0.f);
    acc.w = fmaxf(acc.w, 0.f);
    __nv_bfloat16 h0, l0, h1, l1, h2, l2, h3, l3;
    split_bf16(acc.x, h0, l0); split_bf16(acc.y, h1, l1);
    split_bf16(acc.z, h2, l2); split_bf16(acc.w, h3, l3);
    __nv_bfloat162 H0; H0.x = h0; H0.y = h1;
    __nv_bfloat162 H1; H1.x = h2; H1.y = h3;
    __nv_bfloat162 L0; L0.x = l0; L0.y = l1;
    __nv_bfloat162 L1; L1.x = l2; L1.y = l3;
    const size_t o2 = (size_t)gw * 64 + lane * 2;
    reinterpret_cast<__nv_bfloat162*>(g_hH)[o2]     = H0;
    reinterpret_cast<__nv_bfloat162*>(g_hH)[o2 + 1] = H1;
    reinterpret_cast<__nv_bfloat162*>(g_hL)[o2]     = L0;
    reinterpret_cast<__nv_bfloat162*>(g_hL)[o2 + 1] = L1;
}

__global__ __launch_bounds__(256)
void k_agg2(const float* __restrict__ b2, float* __restrict__ out) {
    const int gw = (blockIdx.x * 256 + threadIdx.x) >> 5;
    if (gw >= NN) return;
    const int lane = threadIdx.x & 31;
    float2 acc = make_float2(0.f, 0.f);
#pragma unroll
    for (int r = 0; r < RR; ++r) {
        const int idx = r * NN + gw;
        const int deg = g_deg[idx];
        if (deg == 0) continue;
        const int beg = g_off[idx];
        float2 s = make_float2(0.f, 0.f);
        for (int bse = 0; bse < deg; bse += 32) {
            const int my = bse + lane;
            const int src_l = (my < deg) ? g_esrc[beg + my] : 0;
            const int n = min(32, deg - bse);
            for (int j = 0; j < n; ++j) {
                const int src = __shfl_sync(~0u, src_l, j);
                const float2 v = *reinterpret_cast<const float2*>(
                    g_Wh2 + ((size_t)r * NN + src) * DOUT + lane * 2);
                s.x += v.x; s.y += v.y;
            }
        }
        const float d = 1.0f / (float)deg;
        const float2 bb = *reinterpret_cast<const float2*>(b2 + r * DOUT + lane * 2);
        acc.x += s.x * d + bb.x;
        acc.y += s.y * d + bb.y;
    }
    *reinterpret_cast<float2*>(out + (size_t)gw * DOUT + lane * 2) = acc;
}

// ==================== launch ====================
extern "C" void kernel_launch(void* const* d_in, const int* in_sizes, int n_in,
                              void* d_out, int out_size) {
    const float* feat  = (const float*)d_in[0];
    const float* W1    = (const float*)d_in[1];
    const float* b1    = (const float*)d_in[2];
    const float* W2    = (const float*)d_in[3];
    const float* b2    = (const float*)d_in[4];
    const int*   edges = (const int*)d_in[5];
    float* out = (float*)d_out;

    void *pFH, *pFL, *pHH, *pHL, *pW1H, *pW1L, *pW2H, *pW2L, *pWh1, *pWh2;
    cudaGetSymbolAddress(&pFH, g_featH);
    cudaGetSymbolAddress(&pFL, g_featL);
    cudaGetSymbolAddress(&pHH, g_hH);
    cudaGetSymbolAddress(&pHL, g_hL);
    cudaGetSymbolAddress(&pW1H, g_w1H);
    cudaGetSymbolAddress(&pW1L, g_w1L);
    cudaGetSymbolAddress(&pW2H, g_w2H);
    cudaGetSymbolAddress(&pW2L, g_w2L);
    cudaGetSymbolAddress(&pWh1, g_Wh1);
    cudaGetSymbolAddress(&pWh2, g_Wh2);

    const int smem1 = (64 + 64 + 128 + 128) * ROWB;  // 104448 B
    const int smem2 = (64 + 64 + 64 + 64) * ROWB;    //  69632 B
    cudaFuncSetAttribute(k_mma<128>, cudaFuncAttributeMaxDynamicSharedMemorySize, smem1);
    cudaFuncSetAttribute(k_mma<64>,  cudaFuncAttributeMaxDynamicSharedMemorySize, smem2);

    dim3 gg((NN + 63) / 64, RR);
    const int aggGrid = (NN * 32 + 255) / 256;

    // 1-3: conversions / weight prep
    k_cvt_feat<<<(NN * DIN / 4 + 255) / 256, 256>>>(feat);
    k_prep_w1<<<(RR * 128 * 128 + 255) / 256, 256>>>(W1);
    k_prep_w2<<<(RR * 128 * 64 + 255) / 256, 256>>>(W2);

    // 4: GEMM1 on tensor cores (kept 4th so ncu captures it)
    k_mma<128><<<gg, 256, smem1>>>((const __nv_bfloat16*)pFH, (const __nv_bfloat16*)pFL,
                                   (const __nv_bfloat16*)pW1H, (const __nv_bfloat16*)pW1L,
                                   (float*)pWh1);

    // 5-10: CSR build
    k_zero<<<(SCAN_N + 255) / 256, 256>>>();
    k_count<<<(RR * EE + 255) / 256, 256>>>(edges);
    k_scan1<<<NBLK, 256>>>();
    k_scan2<<<1, 128>>>();
    k_scan3<<<(SCAN_N + 255) / 256, 256>>>();
    k_bin<<<(RR * EE + 255) / 256, 256>>>(edges);

    // 11: layer-1 aggregate (mean + bias-gate + relu + bf16 split)
    k_agg1<<<aggGrid, 256>>>(b1);

    // 12: GEMM2 on tensor cores
    k_mma<64><<<gg, 256, smem2>>>((const __nv_bfloat16*)pHH, (const __nv_bfloat16*)pHL,
                                  (const __nv_bfloat16*)pW2H, (const __nv_bfloat16*)pW2L,
                                  (float*)pWh2);

    // 13: layer-2 aggregate -> out
    k_agg2<<<aggGrid, 256>>>(b2, out);
}

// round 8
// speedup vs baseline: 1.0004x; 1.0004x over previous
#include <cuda_runtime.h>
#include <cuda_bf16.h>
#include <cstdint>
#include <cstddef>

// Problem constants
#define NN   50000
#define EE   200000
#define RR   4
#define DIN  128
#define DH   128
#define DOUT 64
#define KK   512          // concat-K = RR * 128

#define SCAN_N (RR * NN)
#define CHUNK  2048
#define NBLK   ((SCAN_N + CHUNK - 1) / CHUNK)   // 98

// smem row stride for MMA tiles: 128 bf16 + 8 pad = 272 bytes (bank-rotating)
#define ROWB 272

// -------- scratch (static device globals) --------
__device__ __nv_bfloat16 g_ZH[(size_t)NN * KK];   // agg means, hi split  [N][512]
__device__ __nv_bfloat16 g_ZL[(size_t)NN * KK];   // lo split
__device__ float g_h[NN * DH];                    // relu(layer-1 out) fp32
__device__ __nv_bfloat16 g_w1H[DH * KK];          // W1 stacked^T hi [128 n][512 k]
__device__ __nv_bfloat16 g_w1L[DH * KK];
__device__ __nv_bfloat16 g_w2H[DOUT * KK];        // W2 stacked^T hi [64 n][512 k]
__device__ __nv_bfloat16 g_w2L[DOUT * KK];
__device__ unsigned char g_gate[NN];              // per-node etype gate bits
__device__ int g_deg[SCAN_N];
__device__ int g_off[SCAN_N];
__device__ int g_cur[SCAN_N];
__device__ int g_bsum[NBLK];
__device__ int g_esrc[RR * EE];

__device__ __forceinline__ uint32_t smem_to_u32(const void* p) {
    uint32_t a;
    asm("{ .reg .u64 t; cvta.to.shared.u64 t, %1; cvt.u32.u64 %0, t; }"
        : "=r"(a) : "l"(p));
    return a;
}

#define LDSM_X4(r0, r1, r2, r3, addr) \
    asm volatile("ldmatrix.sync.aligned.m8n8.x4.shared.b16 {%0,%1,%2,%3}, [%4];" \
                 : "=r"(r0), "=r"(r1), "=r"(r2), "=r"(r3) : "r"(addr))

#define MMA_BF16(c, a, b0, b1) \
    asm volatile("mma.sync.aligned.m16n8k16.row.col.f32.bf16.bf16.f32 " \
                 "{%0,%1,%2,%3},{%4,%5,%6,%7},{%8,%9},{%0,%1,%2,%3};" \
                 : "+f"((c)[0]), "+f"((c)[1]), "+f"((c)[2]), "+f"((c)[3]) \
                 : "r"((a)[0]), "r"((a)[1]), "r"((a)[2]), "r"((a)[3]), \
                   "r"(b0), "r"(b1))

// -------- precision split --------
__device__ __forceinline__ void split_bf16(float v, __nv_bfloat16& h, __nv_bfloat16& l) {
    h = __float2bfloat16(v);
    l = __float2bfloat16(v - __bfloat162float(h));
}

// ==================== weight prep: stacked transpose + split ====================
// W1 [r][k=128][n=128] -> w1T [n][r*128+k]
__global__ void k_prep_w1(const float* __restrict__ W) {
    int i = blockIdx.x * 256 + threadIdx.x;
    if (i >= RR * 128 * 128) return;
    int r = i >> 14, k = (i >> 7) & 127, n = i & 127;
    float w = W[i];
    __nv_bfloat16 h, l; split_bf16(w, h, l);
    int o = n * KK + r * 128 + k;
    g_w1H[o] = h; g_w1L[o] = l;
}
// W2 [r][k=128][n=64] -> w2T [n][r*128+k]
__global__ void k_prep_w2(const float* __restrict__ W) {
    int i = blockIdx.x * 256 + threadIdx.x;
    if (i >= RR * 128 * 64) return;
    int r = i / 8192, k = (i >> 6) & 127, n = i & 63;
    float w = W[i];
    __nv_bfloat16 h, l; split_bf16(w, h, l);
    int o = n * KK + r * 128 + k;
    g_w2H[o] = h; g_w2L[o] = l;
}

// ==================== degree / CSR build ====================
__global__ void k_zero() {
    int i = blockIdx.x * 256 + threadIdx.x;
    if (i < SCAN_N) { g_deg[i] = 0; g_cur[i] = 0; }
}
__global__ void k_count(const int* __restrict__ edges) {
    int i = blockIdx.x * 256 + threadIdx.x;
    if (i >= RR * EE) return;
    int r = i / EE, e = i - r * EE;
    int dst = edges[r * 2 * EE + EE + e];
    atomicAdd(&g_deg[r * NN + dst], 1);
}
__global__ __launch_bounds__(256) void k_scan1() {
    __shared__ int wsum[8];
    const int b = blockIdx.x, t = threadIdx.x;
    const int base = b * CHUNK + t * 8;
    int v[8]; int s = 0;
#pragma unroll
    for (int i = 0; i < 8; ++i) {
        int idx = base + i;
        int x = (idx < SCAN_N) ? g_deg[idx] : 0;
        v[i] = s; s += x;
    }
    const int lane = t & 31, w = t >> 5;
    int x = s;
#pragma unroll
    for (int o = 1; o < 32; o <<= 1) {
        int n = __shfl_up_sync(~0u, x, o);
        if (lane >= o) x += n;
    }
    if (lane == 31) wsum[w] = x;
    __syncthreads();
    if (t == 0) {
        int acc = 0;
#pragma unroll
        for (int i = 0; i < 8; ++i) { int tmp = wsum[i]; wsum[i] = acc; acc += tmp; }
        g_bsum[b] = acc;
    }
    __syncthreads();
    const int toff = wsum[w] + (x - s);
#pragma unroll
    for (int i = 0; i < 8; ++i) {
        int idx = base + i;
        if (idx < SCAN_N) g_off[idx] = toff + v[i];
    }
}
__global__ void k_scan2() {
    __shared__ int ws[4];
    const int t = threadIdx.x;
    const int v = (t < NBLK) ? g_bsum[t] : 0;
    const int lane = t & 31, w = t >> 5;
    int x = v;
#pragma unroll
    for (int o = 1; o < 32; o <<= 1) {
        int n = __shfl_up_sync(~0u, x, o);
        if (lane >= o) x += n;
    }
    if (lane == 31) ws[w] = x;
    __syncthreads();
    if (t == 0) {
        int acc = 0;
#pragma unroll
        for (int i = 0; i < 4; ++i) { int tmp = ws[i]; ws[i] = acc; acc += tmp; }
    }
    __syncthreads();
    if (t < NBLK) g_bsum[t] = (x - v) + ws[w];
}
__global__ void k_scan3() {
    int i = blockIdx.x * 256 + threadIdx.x;
    if (i < SCAN_N) g_off[i] += g_bsum[i >> 11];
}
__global__ void k_bin(const int* __restrict__ edges) {
    int i = blockIdx.x * 256 + threadIdx.x;
    if (i >= RR * EE) return;
    int r = i / EE, e = i - r * EE;
    const int* eb = edges + r * 2 * EE;
    int src = eb[e];
    int dst = eb[EE + e];
    int idx = r * NN + dst;
    int pos = g_off[idx] + atomicAdd(&g_cur[idx], 1);
    g_esrc[pos] = src;
}

// ==================== aggregate-first gather (mean of F rows) ====================
// Per node, per etype: Z_r = mean over in-edges of F[src] (128 fp32), split to
// bf16 hi/lo, stored concat: Z[node][r*128 + c]. Also writes g_gate mask.
__global__ __launch_bounds__(256)
void k_aggZ(const float* __restrict__ F,
            __nv_bfloat16* __restrict__ ZH, __nv_bfloat16* __restrict__ ZL) {
    const int gw = (blockIdx.x * 256 + threadIdx.x) >> 5;
    if (gw >= NN) return;
    const int lane = threadIdx.x & 31;
    unsigned mask = 0;
#pragma unroll
    for (int r = 0; r < RR; ++r) {
        const int idx = r * NN + gw;
        const int deg = g_deg[idx];
        float4 s = make_float4(0.f, 0.f, 0.f, 0.f);
        if (deg > 0) {
            mask |= 1u << r;
            const int beg = g_off[idx];
            for (int bse = 0; bse < deg; bse += 32) {
                const int my = bse + lane;
                const int src_l = (my < deg) ? g_esrc[beg + my] : 0;
                const int n = min(32, deg - bse);
                for (int j = 0; j < n; ++j) {
                    const int src = __shfl_sync(~0u, src_l, j);
                    const float4 v = *reinterpret_cast<const float4*>(
                        F + (size_t)src * 128 + lane * 4);
                    s.x += v.x; s.y += v.y; s.z += v.z; s.w += v.w;
                }
            }
            const float d = 1.0f / (float)deg;
            s.x *= d; s.y *= d; s.z *= d; s.w *= d;
        }
        __nv_bfloat16 h0, l0, h1, l1, h2, l2, h3, l3;
        split_bf16(s.x, h0, l0); split_bf16(s.y, h1, l1);
        split_bf16(s.z, h2, l2); split_bf16(s.w, h3, l3);
        __nv_bfloat162 H0; H0.x = h0; H0.y = h1;
        __nv_bfloat162 H1; H1.x = h2; H1.y = h3;
        __nv_bfloat162 L0; L0.x = l0; L0.y = l1;
        __nv_bfloat162 L1; L1.x = l2; L1.y = l3;
        const size_t o2 = ((size_t)gw * KK + r * 128 + lane * 4) >> 1;  // bf162 idx
        reinterpret_cast<__nv_bfloat162*>(ZH)[o2]     = H0;
        reinterpret_cast<__nv_bfloat162*>(ZH)[o2 + 1] = H1;
        reinterpret_cast<__nv_bfloat162*>(ZL)[o2]     = L0;
        reinterpret_cast<__nv_bfloat162*>(ZL)[o2 + 1] = L1;
    }
    if (lane == 0) g_gate[gw] = (unsigned char)mask;
}

// ==================== bf16x3 GEMM, K=512, fused epilogue ====================
// C = A @ B^T (+ gated bias) (+relu). A [N][512] row-major hi/lo; B [NB][512].
// CTA: 256 thr = 8 warps, tile 64m x NB n; K streamed in 4 chunks of 128.
// Warp grid 2m x 4n: warp = 32m x NB/4 n; NT = NB/64.
template <int ROWS>
__device__ __forceinline__ void load_tile512(char* dst, const __nv_bfloat16* __restrict__ src,
                                             int valid_rows, int tid) {
#pragma unroll
    for (int i = 0; i < ROWS * 16 / 256; ++i) {
        const int j = i * 256 + tid;
        const int row = j >> 4;
        const int c16 = j & 15;
        uint4 v = make_uint4(0u, 0u, 0u, 0u);
        if (row < valid_rows)
            v = *reinterpret_cast<const uint4*>(src + (size_t)row * KK + c16 * 8);
        *reinterpret_cast<uint4*>(dst + row * ROWB + c16 * 16) = v;
    }
}

template <int NB, bool RELU>   // NB=128 layer1, NB=64 layer2
__global__ __launch_bounds__(256, 2)
void k_mma(const __nv_bfloat16* __restrict__ AH, const __nv_bfloat16* __restrict__ AL,
           const __nv_bfloat16* __restrict__ BH, const __nv_bfloat16* __restrict__ BL,
           const float* __restrict__ bias,      // [RR][NB]
           float* __restrict__ C)               // [N][NB]
{
    constexpr int NT = NB / 64;
    extern __shared__ __align__(16) char smem[];
    char* sAh = smem;
    char* sAl = sAh + 64 * ROWB;
    char* sBh = sAl + 64 * ROWB;
    char* sBl = sBh + NB * ROWB;
    float* bs = reinterpret_cast<float*>(sBl + NB * ROWB);  // [RR*NB]

    const int tid  = threadIdx.x;
    const int lane = tid & 31;
    const int wid  = tid >> 5;
    const int m0   = blockIdx.x * 64;
    const int validA = (NN - m0) < 64 ? (NN - m0) : 64;

    // bias to smem
#pragma unroll
    for (int i = tid; i < RR * NB; i += 256) bs[i] = bias[i];

    const int wm = (wid >> 2) * 32;
    const int wn = (wid & 3) * (NB / 4);
    const int aoff = (lane & 15) * ROWB + (lane >> 4) * 16;
    const int boff = ((lane & 7) + ((lane >> 4) << 3)) * ROWB + ((lane >> 3) & 1) * 16;

    const uint32_t uAh = smem_to_u32(sAh);
    const uint32_t uAl = smem_to_u32(sAl);
    const uint32_t uBh = smem_to_u32(sBh);
    const uint32_t uBl = smem_to_u32(sBl);

    float acc[2][NT * 2][4];
#pragma unroll
    for (int mt = 0; mt < 2; ++mt)
#pragma unroll
        for (int nt = 0; nt < NT * 2; ++nt)
#pragma unroll
            for (int q = 0; q < 4; ++q) acc[mt][nt][q] = 0.f;

    for (int kc = 0; kc < 4; ++kc) {
        if (kc) __syncthreads();
        load_tile512<64>(sAh, AH + (size_t)m0 * KK + kc * 128, validA, tid);
        load_tile512<64>(sAl, AL + (size_t)m0 * KK + kc * 128, validA, tid);
        load_tile512<NB>(sBh, BH + kc * 128, NB, tid);
        load_tile512<NB>(sBl, BL + kc * 128, NB, tid);
        __syncthreads();

#pragma unroll
        for (int ks = 0; ks < 8; ++ks) {
            const int kb = ks * 32;
            uint32_t ah[2][4], al[2][4];
#pragma unroll
            for (int mt = 0; mt < 2; ++mt) {
                const uint32_t base = (wm + mt * 16) * ROWB + aoff + kb;
                LDSM_X4(ah[mt][0], ah[mt][1], ah[mt][2], ah[mt][3], uAh + base);
                LDSM_X4(al[mt][0], al[mt][1], al[mt][2], al[mt][3], uAl + base);
            }
#pragma unroll
            for (int jt = 0; jt < NT; ++jt) {
                const uint32_t bbase = (wn + jt * 16) * ROWB + boff + kb;
                uint32_t bh[4], bl[4];
                LDSM_X4(bh[0], bh[1], bh[2], bh[3], uBh + bbase);
                LDSM_X4(bl[0], bl[1], bl[2], bl[3], uBl + bbase);
#pragma unroll
                for (int mt = 0; mt < 2; ++mt) {
                    MMA_BF16(acc[mt][2 * jt],     ah[mt], bh[0], bh[1]);
                    MMA_BF16(acc[mt][2 * jt + 1], ah[mt], bh[2], bh[3]);
                    MMA_BF16(acc[mt][2 * jt],     ah[mt], bl[0], bl[1]);
                    MMA_BF16(acc[mt][2 * jt + 1], ah[mt], bl[2], bl[3]);
                    MMA_BF16(acc[mt][2 * jt],     al[mt], bh[0], bh[1]);
                    MMA_BF16(acc[mt][2 * jt + 1], al[mt], bh[2], bh[3]);
                }
            }
        }
    }

    // fused epilogue: + gated bias, optional relu, direct store
#pragma unroll
    for (int mt = 0; mt < 2; ++mt) {
        const int rbase = m0 + wm + mt * 16 + (lane >> 2);
#pragma unroll
        for (int half = 0; half < 2; ++half) {
            const int row = rbase + half * 8;
            if (row >= NN) continue;
            const unsigned g = g_gate[row];
#pragma unroll
            for (int nt = 0; nt < NT * 2; ++nt) {
                const int col = wn + nt * 8 + (lane & 3) * 2;
                float bx = 0.f, by = 0.f;
#pragma unroll
                for (int r = 0; r < RR; ++r) {
                    if ((g >> r) & 1) {
                        bx += bs[r * NB + col];
                        by += bs[r * NB + col + 1];
                    }
                }
                float x = acc[mt][nt][half * 2 + 0] + bx;
                float y = acc[mt][nt][half * 2 + 1] + by;
                if (RELU) { x = fmaxf(x, 0.f); y = fmaxf(y, 0.f); }
                *reinterpret_cast<float2*>(C + (size_t)row * NB + col) =
                    make_float2(x, y);
            }
        }
    }
}

// ==================== launch ====================
extern "C" void kernel_launch(void* const* d_in, const int* in_sizes, int n_in,
                              void* d_out, int out_size) {
    const float* feat  = (const float*)d_in[0];
    const float* W1    = (const float*)d_in[1];
    const float* b1    = (const float*)d_in[2];
    const float* W2    = (const float*)d_in[3];
    const float* b2    = (const float*)d_in[4];
    const int*   edges = (const int*)d_in[5];
    float* out = (float*)d_out;

    void *pZH, *pZL, *pH, *pW1H, *pW1L, *pW2H, *pW2L;
    cudaGetSymbolAddress(&pZH, g_ZH);
    cudaGetSymbolAddress(&pZL, g_ZL);
    cudaGetSymbolAddress(&pH,  g_h);
    cudaGetSymbolAddress(&pW1H, g_w1H);
    cudaGetSymbolAddress(&pW1L, g_w1L);
    cudaGetSymbolAddress(&pW2H, g_w2H);
    cudaGetSymbolAddress(&pW2L, g_w2L);

    const int smem1 = (64 + 64 + 128 + 128) * ROWB + RR * 128 * 4;  // 106496
    const int smem2 = (64 + 64 + 64 + 64) * ROWB + RR * 64 * 4;     //  70656
    cudaFuncSetAttribute(k_mma<128, true>, cudaFuncAttributeMaxDynamicSharedMemorySize, smem1);
    cudaFuncSetAttribute(k_mma<64, false>, cudaFuncAttributeMaxDynamicSharedMemorySize, smem2);

    const dim3 gg((NN + 63) / 64);
    const int aggGrid = (NN * 32 + 255) / 256;

    // CSR build
    k_zero<<<(SCAN_N + 255) / 256, 256>>>();
    k_count<<<(RR * EE + 255) / 256, 256>>>(edges);
    k_scan1<<<NBLK, 256>>>();
    k_scan2<<<1, 128>>>();
    k_scan3<<<(SCAN_N + 255) / 256, 256>>>();
    k_bin<<<(RR * EE + 255) / 256, 256>>>(edges);

    // weight prep
    k_prep_w1<<<(RR * 128 * 128 + 255) / 256, 256>>>(W1);
    k_prep_w2<<<(RR * 128 * 64 + 255) / 256, 256>>>(W2);

    // layer 1: aggregate feat -> Z, then GEMM (K=512) with bias+relu epilogue
    k_aggZ<<<aggGrid, 256>>>(feat, (__nv_bfloat16*)pZH, (__nv_bfloat16*)pZL);
    k_mma<128, true><<<gg, 256, smem1>>>(
        (const __nv_bfloat16*)pZH, (const __nv_bfloat16*)pZL,
        (const __nv_bfloat16*)pW1H, (const __nv_bfloat16*)pW1L, b1, (float*)pH);

    // layer 2: aggregate h -> Z (reuse buffers), GEMM writes out directly
    k_aggZ<<<aggGrid, 256>>>((const float*)pH, (__nv_bfloat16*)pZH, (__nv_bfloat16*)pZL);
    k_mma<64, false><<<gg, 256, smem2>>>(
        (const __nv_bfloat16*)pZH, (const __nv_bfloat16*)pZL,
        (const __nv_bfloat16*)pW2H, (const __nv_bfloat16*)pW2L, b2, out);
}

// round 9
// speedup vs baseline: 1.2656x; 1.2651x over previous
#include <cuda_runtime.h>
#include <cuda_fp16.h>
#include <cstdint>
#include <cstddef>

// Problem constants
#define NN   50000
#define EE   200000
#define RR   4
#define DIN  128
#define DH   128
#define DOUT 64
#define KK   512          // concat-K = RR * 128

#define SCAN_N (RR * NN)
#define CHUNK  2048
#define NBLK   ((SCAN_N + CHUNK - 1) / CHUNK)   // 98

// smem row stride for MMA tiles: 128 fp16 + pad = 272 bytes (bank-rotating)
#define ROWB 272

// -------- scratch (static device globals) --------
__device__ __half g_Z[(size_t)NN * KK];     // agg means, fp16  [N][512]
__device__ float  g_h[NN * DH];             // relu(layer-1 out) fp32
__device__ __half g_w1H[DH * KK];           // W1 stacked^T hi [128 n][512 k]
__device__ __half g_w1L[DH * KK];           // W1 stacked^T lo
__device__ __half g_w2H[DOUT * KK];         // W2 stacked^T hi [64 n][512 k]
__device__ __half g_w2L[DOUT * KK];
__device__ unsigned char g_gate[NN];        // per-node etype gate bits
__device__ int g_deg[SCAN_N];
__device__ int g_off[SCAN_N];
__device__ int g_cur[SCAN_N];
__device__ int g_bsum[NBLK];
__device__ int g_esrc[RR * EE];

__device__ __forceinline__ uint32_t smem_to_u32(const void* p) {
    uint32_t a;
    asm("{ .reg .u64 t; cvta.to.shared.u64 t, %1; cvt.u32.u64 %0, t; }"
        : "=r"(a) : "l"(p));
    return a;
}

#define LDSM_X4(r0, r1, r2, r3, addr) \
    asm volatile("ldmatrix.sync.aligned.m8n8.x4.shared.b16 {%0,%1,%2,%3}, [%4];" \
                 : "=r"(r0), "=r"(r1), "=r"(r2), "=r"(r3) : "r"(addr))

#define MMA_F16(c, a, b0, b1) \
    asm volatile("mma.sync.aligned.m16n8k16.row.col.f32.f16.f16.f32 " \
                 "{%0,%1,%2,%3},{%4,%5,%6,%7},{%8,%9},{%0,%1,%2,%3};" \
                 : "+f"((c)[0]), "+f"((c)[1]), "+f"((c)[2]), "+f"((c)[3]) \
                 : "r"((a)[0]), "r"((a)[1]), "r"((a)[2]), "r"((a)[3]), \
                   "r"(b0), "r"(b1))

// -------- fp16 hi/lo split for weights --------
__device__ __forceinline__ void split_f16(float v, __half& h, __half& l) {
    h = __float2half(v);
    l = __float2half(v - __half2float(h));
}

// ==================== weight prep: stacked transpose + fp16 split ====================
// W1 [r][k=128][n=128] -> w1T [n][r*128+k]
__global__ void k_prep_w1(const float* __restrict__ W) {
    int i = blockIdx.x * 256 + threadIdx.x;
    if (i >= RR * 128 * 128) return;
    int r = i >> 14, k = (i >> 7) & 127, n = i & 127;
    float w = W[i];
    __half h, l; split_f16(w, h, l);
    int o = n * KK + r * 128 + k;
    g_w1H[o] = h; g_w1L[o] = l;
}
// W2 [r][k=128][n=64] -> w2T [n][r*128+k]
__global__ void k_prep_w2(const float* __restrict__ W) {
    int i = blockIdx.x * 256 + threadIdx.x;
    if (i >= RR * 128 * 64) return;
    int r = i / 8192, k = (i >> 6) & 127, n = i & 63;
    float w = W[i];
    __half h, l; split_f16(w, h, l);
    int o = n * KK + r * 128 + k;
    g_w2H[o] = h; g_w2L[o] = l;
}

// ==================== degree / CSR build ====================
__global__ void k_zero() {
    int i = blockIdx.x * 256 + threadIdx.x;
    if (i < SCAN_N) { g_deg[i] = 0; g_cur[i] = 0; }
}
__global__ void k_count(const int* __restrict__ edges) {
    int i = blockIdx.x * 256 + threadIdx.x;
    if (i >= RR * EE) return;
    int r = i / EE, e = i - r * EE;
    int dst = edges[r * 2 * EE + EE + e];
    atomicAdd(&g_deg[r * NN + dst], 1);
}
__global__ __launch_bounds__(256) void k_scan1() {
    __shared__ int wsum[8];
    const int b = blockIdx.x, t = threadIdx.x;
    const int base = b * CHUNK + t * 8;
    int v[8]; int s = 0;
#pragma unroll
    for (int i = 0; i < 8; ++i) {
        int idx = base + i;
        int x = (idx < SCAN_N) ? g_deg[idx] : 0;
        v[i] = s; s += x;
    }
    const int lane = t & 31, w = t >> 5;
    int x = s;
#pragma unroll
    for (int o = 1; o < 32; o <<= 1) {
        int n = __shfl_up_sync(~0u, x, o);
        if (lane >= o) x += n;
    }
    if (lane == 31) wsum[w] = x;
    __syncthreads();
    if (t == 0) {
        int acc = 0;
#pragma unroll
        for (int i = 0; i < 8; ++i) { int tmp = wsum[i]; wsum[i] = acc; acc += tmp; }
        g_bsum[b] = acc;
    }
    __syncthreads();
    const int toff = wsum[w] + (x - s);
#pragma unroll
    for (int i = 0; i < 8; ++i) {
        int idx = base + i;
        if (idx < SCAN_N) g_off[idx] = toff + v[i];
    }
}
__global__ void k_scan2() {
    __shared__ int ws[4];
    const int t = threadIdx.x;
    const int v = (t < NBLK) ? g_bsum[t] : 0;
    const int lane = t & 31, w = t >> 5;
    int x = v;
#pragma unroll
    for (int o = 1; o < 32; o <<= 1) {
        int n = __shfl_up_sync(~0u, x, o);
        if (lane >= o) x += n;
    }
    if (lane == 31) ws[w] = x;
    __syncthreads();
    if (t == 0) {
        int acc = 0;
#pragma unroll
        for (int i = 0; i < 4; ++i) { int tmp = ws[i]; ws[i] = acc; acc += tmp; }
    }
    __syncthreads();
    if (t < NBLK) g_bsum[t] = (x - v) + ws[w];
}
__global__ void k_scan3() {
    int i = blockIdx.x * 256 + threadIdx.x;
    if (i < SCAN_N) g_off[i] += g_bsum[i >> 11];
}
__global__ void k_bin(const int* __restrict__ edges) {
    int i = blockIdx.x * 256 + threadIdx.x;
    if (i >= RR * EE) return;
    int r = i / EE, e = i - r * EE;
    const int* eb = edges + r * 2 * EE;
    int src = eb[e];
    int dst = eb[EE + e];
    int idx = r * NN + dst;
    int pos = g_off[idx] + atomicAdd(&g_cur[idx], 1);
    g_esrc[pos] = src;
}

// ==================== aggregate-first gather (mean of F rows) ====================
// Per node, per etype: Z_r = mean over in-edges of F[src] (128 fp32), rounded
// to fp16, stored concat: Z[node][r*128 + c]. Also writes g_gate mask.
__global__ __launch_bounds__(256)
void k_aggZ(const float* __restrict__ F, __half* __restrict__ Z) {
    const int gw = (blockIdx.x * 256 + threadIdx.x) >> 5;
    if (gw >= NN) return;
    const int lane = threadIdx.x & 31;
    unsigned mask = 0;
#pragma unroll
    for (int r = 0; r < RR; ++r) {
        const int idx = r * NN + gw;
        const int deg = g_deg[idx];
        float4 s = make_float4(0.f, 0.f, 0.f, 0.f);
        if (deg > 0) {
            mask |= 1u << r;
            const int beg = g_off[idx];
            for (int bse = 0; bse < deg; bse += 32) {
                const int my = bse + lane;
                const int src_l = (my < deg) ? g_esrc[beg + my] : 0;
                const int n = min(32, deg - bse);
                for (int j = 0; j < n; ++j) {
                    const int src = __shfl_sync(~0u, src_l, j);
                    const float4 v = *reinterpret_cast<const float4*>(
                        F + (size_t)src * 128 + lane * 4);
                    s.x += v.x; s.y += v.y; s.z += v.z; s.w += v.w;
                }
            }
            const float d = 1.0f / (float)deg;
            s.x *= d; s.y *= d; s.z *= d; s.w *= d;
        }
        __half2 p0 = __floats2half2_rn(s.x, s.y);
        __half2 p1 = __floats2half2_rn(s.z, s.w);
        const size_t o2 = ((size_t)gw * KK + r * 128 + lane * 4) >> 1;  // half2 idx
        reinterpret_cast<__half2*>(Z)[o2]     = p0;
        reinterpret_cast<__half2*>(Z)[o2 + 1] = p1;
    }
    if (lane == 0) g_gate[gw] = (unsigned char)mask;
}

// ==================== fp16x2 GEMM, K=512, fused epilogue ====================
// C = A @ (Bh+Bl)^T (+ gated bias) (+relu). A [N][512] fp16; B [NB][512] hi/lo.
// CTA: 256 thr = 8 warps, tile 128m x NB n; K streamed in 4 chunks of 128.
// Warp grid 2m x 4n: warp = 64m x NB/4 n; mt=4 m16 tiles; NT = NB/64 jt-steps.
template <int ROWS>
__device__ __forceinline__ void load_tile512(char* dst, const __half* __restrict__ src,
                                             int valid_rows, int tid) {
#pragma unroll
    for (int i = 0; i < ROWS * 16 / 256; ++i) {
        const int j = i * 256 + tid;
        const int row = j >> 4;
        const int c16 = j & 15;
        uint4 v = make_uint4(0u, 0u, 0u, 0u);
        if (row < valid_rows)
            v = *reinterpret_cast<const uint4*>(src + (size_t)row * KK + c16 * 8);
        *reinterpret_cast<uint4*>(dst + row * ROWB + c16 * 16) = v;
    }
}

template <int NB, bool RELU>   // NB=128 layer1, NB=64 layer2
__global__ __launch_bounds__(256, 2)
void k_mma(const __half* __restrict__ A,
           const __half* __restrict__ BH, const __half* __restrict__ BL,
           const float* __restrict__ bias,      // [RR][NB]
           float* __restrict__ C)               // [N][NB]
{
    constexpr int NT = NB / 64;
    extern __shared__ __align__(16) char smem[];
    char* sA  = smem;
    char* sBh = sA + 128 * ROWB;
    char* sBl = sBh + NB * ROWB;
    float* bs = reinterpret_cast<float*>(sBl + NB * ROWB);  // [RR*NB]

    const int tid  = threadIdx.x;
    const int lane = tid & 31;
    const int wid  = tid >> 5;
    const int m0   = blockIdx.x * 128;
    const int validA = (NN - m0) < 128 ? (NN - m0) : 128;

#pragma unroll
    for (int i = tid; i < RR * NB; i += 256) bs[i] = bias[i];

    const int wm = (wid >> 2) * 64;          // warp m offset (2 groups of 64)
    const int wn = (wid & 3) * (NB / 4);     // warp n offset (4 groups)
    const int aoff = (lane & 15) * ROWB + (lane >> 4) * 16;
    const int boff = ((lane & 7) + ((lane >> 4) << 3)) * ROWB + ((lane >> 3) & 1) * 16;

    const uint32_t uA  = smem_to_u32(sA);
    const uint32_t uBh = smem_to_u32(sBh);
    const uint32_t uBl = smem_to_u32(sBl);

    float acc[4][NT * 2][4];
#pragma unroll
    for (int mt = 0; mt < 4; ++mt)
#pragma unroll
        for (int nt = 0; nt < NT * 2; ++nt)
#pragma unroll
            for (int q = 0; q < 4; ++q) acc[mt][nt][q] = 0.f;

    for (int kc = 0; kc < 4; ++kc) {
        if (kc) __syncthreads();
        load_tile512<128>(sA, A + (size_t)m0 * KK + kc * 128, validA, tid);
        load_tile512<NB>(sBh, BH + kc * 128, NB, tid);
        load_tile512<NB>(sBl, BL + kc * 128, NB, tid);
        __syncthreads();

#pragma unroll
        for (int ks = 0; ks < 8; ++ks) {
            const int kb = ks * 32;
            uint32_t a[4][4];
#pragma unroll
            for (int mt = 0; mt < 4; ++mt) {
                const uint32_t base = (wm + mt * 16) * ROWB + aoff + kb;
                LDSM_X4(a[mt][0], a[mt][1], a[mt][2], a[mt][3], uA + base);
            }
#pragma unroll
            for (int jt = 0; jt < NT; ++jt) {
                const uint32_t bbase = (wn + jt * 16) * ROWB + boff + kb;
                uint32_t bh[4], bl[4];
                LDSM_X4(bh[0], bh[1], bh[2], bh[3], uBh + bbase);
                LDSM_X4(bl[0], bl[1], bl[2], bl[3], uBl + bbase);
#pragma unroll
                for (int mt = 0; mt < 4; ++mt) {
                    MMA_F16(acc[mt][2 * jt],     a[mt], bh[0], bh[1]);
                    MMA_F16(acc[mt][2 * jt + 1], a[mt], bh[2], bh[3]);
                    MMA_F16(acc[mt][2 * jt],     a[mt], bl[0], bl[1]);
                    MMA_F16(acc[mt][2 * jt + 1], a[mt], bl[2], bl[3]);
                }
            }
        }
    }

    // fused epilogue: + gated bias, optional relu, direct store
#pragma unroll
    for (int mt = 0; mt < 4; ++mt) {
        const int rbase = m0 + wm + mt * 16 + (lane >> 2);
#pragma unroll
        for (int half = 0; half < 2; ++half) {
            const int row = rbase + half * 8;
            if (row >= NN) continue;
            const unsigned g = g_gate[row];
#pragma unroll
            for (int nt = 0; nt < NT * 2; ++nt) {
                const int col = wn + nt * 8 + (lane & 3) * 2;
                float bx = 0.f, by = 0.f;
#pragma unroll
                for (int r = 0; r < RR; ++r) {
                    if ((g >> r) & 1) {
                        bx += bs[r * NB + col];
                        by += bs[r * NB + col + 1];
                    }
                }
                float x = acc[mt][nt][half * 2 + 0] + bx;
                float y = acc[mt][nt][half * 2 + 1] + by;
                if (RELU) { x = fmaxf(x, 0.f); y = fmaxf(y, 0.f); }
                *reinterpret_cast<float2*>(C + (size_t)row * NB + col) =
                    make_float2(x, y);
            }
        }
    }
}

// ==================== launch ====================
extern "C" void kernel_launch(void* const* d_in, const int* in_sizes, int n_in,
                              void* d_out, int out_size) {
    const float* feat  = (const float*)d_in[0];
    const float* W1    = (const float*)d_in[1];
    const float* b1    = (const float*)d_in[2];
    const float* W2    = (const float*)d_in[3];
    const float* b2    = (const float*)d_in[4];
    const int*   edges = (const int*)d_in[5];
    float* out = (float*)d_out;

    void *pZ, *pH, *pW1H, *pW1L, *pW2H, *pW2L;
    cudaGetSymbolAddress(&pZ,  g_Z);
    cudaGetSymbolAddress(&pH,  g_h);
    cudaGetSymbolAddress(&pW1H, g_w1H);
    cudaGetSymbolAddress(&pW1L, g_w1L);
    cudaGetSymbolAddress(&pW2H, g_w2H);
    cudaGetSymbolAddress(&pW2L, g_w2L);

    const int smem1 = (128 + 128 + 128) * ROWB + RR * 128 * 4;  // 106496
    const int smem2 = (128 + 64 + 64) * ROWB + RR * 64 * 4;     //  70656
    cudaFuncSetAttribute(k_mma<128, true>, cudaFuncAttributeMaxDynamicSharedMemorySize, smem1);
    cudaFuncSetAttribute(k_mma<64, false>, cudaFuncAttributeMaxDynamicSharedMemorySize, smem2);

    const dim3 gg((NN + 127) / 128);
    const int aggGrid = (NN * 32 + 255) / 256;

    // CSR build
    k_zero<<<(SCAN_N + 255) / 256, 256>>>();
    k_count<<<(RR * EE + 255) / 256, 256>>>(edges);
    k_scan1<<<NBLK, 256>>>();
    k_scan2<<<1, 128>>>();
    k_scan3<<<(SCAN_N + 255) / 256, 256>>>();
    k_bin<<<(RR * EE + 255) / 256, 256>>>(edges);

    // weight prep
    k_prep_w1<<<(RR * 128 * 128 + 255) / 256, 256>>>(W1);
    k_prep_w2<<<(RR * 128 * 64 + 255) / 256, 256>>>(W2);

    // layer 1: aggregate feat -> Z, GEMM (K=512) with bias+relu epilogue
    k_aggZ<<<aggGrid, 256>>>(feat, (__half*)pZ);
    k_mma<128, true><<<gg, 256, smem1>>>(
        (const __half*)pZ, (const __half*)pW1H, (const __half*)pW1L, b1, (float*)pH);

    // layer 2: aggregate h -> Z, GEMM writes out directly
    k_aggZ<<<aggGrid, 256>>>((const float*)pH, (__half*)pZ);
    k_mma<64, false><<<gg, 256, smem2>>>(
        (const __half*)pZ, (const __half*)pW2H, (const __half*)pW2L, b2, out);
}

// round 10
// speedup vs baseline: 1.3758x; 1.0871x over previous
#include <cuda_runtime.h>
#include <cuda_fp16.h>
#include <cstdint>
#include <cstddef>

// Problem constants
#define NN   50000
#define EE   200000
#define RR   4
#define DIN  128
#define DH   128
#define DOUT 64
#define KK   512          // concat-K = RR * 128

#define SCAN_N (RR * NN)
#define CHUNK  2048
#define NBLK   ((SCAN_N + CHUNK - 1) / CHUNK)   // 98

// smem row stride for MMA tiles: 128 fp16 + pad = 272 bytes (bank-rotating)
#define ROWB 272

// -------- scratch (static device globals) --------
__device__ __half g_Z[(size_t)NN * KK];     // agg means, fp16  [N][512]
__device__ __half g_feat16[(size_t)NN * DIN];  // feat rounded to fp16
__device__ __half g_h16[(size_t)NN * DH];      // relu(layer-1 out), fp16
__device__ __half g_w1H[DH * KK];           // W1 stacked^T hi [128 n][512 k]
__device__ __half g_w1L[DH * KK];           // W1 stacked^T lo
__device__ __half g_w2H[DOUT * KK];         // W2 stacked^T hi [64 n][512 k]
__device__ __half g_w2L[DOUT * KK];
__device__ unsigned char g_gate[NN];        // per-node etype gate bits
__device__ int g_deg[SCAN_N];
__device__ int g_off[SCAN_N];
__device__ int g_cur[SCAN_N];
__device__ int g_bsum[NBLK];
__device__ int g_esrc[RR * EE];

__device__ __forceinline__ uint32_t smem_to_u32(const void* p) {
    uint32_t a;
    asm("{ .reg .u64 t; cvta.to.shared.u64 t, %1; cvt.u32.u64 %0, t; }"
        : "=r"(a) : "l"(p));
    return a;
}

#define LDSM_X4(r0, r1, r2, r3, addr) \
    asm volatile("ldmatrix.sync.aligned.m8n8.x4.shared.b16 {%0,%1,%2,%3}, [%4];" \
                 : "=r"(r0), "=r"(r1), "=r"(r2), "=r"(r3) : "r"(addr))

#define MMA_F16(c, a, b0, b1) \
    asm volatile("mma.sync.aligned.m16n8k16.row.col.f32.f16.f16.f32 " \
                 "{%0,%1,%2,%3},{%4,%5,%6,%7},{%8,%9},{%0,%1,%2,%3};" \
                 : "+f"((c)[0]), "+f"((c)[1]), "+f"((c)[2]), "+f"((c)[3]) \
                 : "r"((a)[0]), "r"((a)[1]), "r"((a)[2]), "r"((a)[3]), \
                   "r"(b0), "r"(b1))

// -------- fp16 hi/lo split for weights --------
__device__ __forceinline__ void split_f16(float v, __half& h, __half& l) {
    h = __float2half(v);
    l = __float2half(v - __half2float(h));
}

// ==================== prep kernels ====================
__global__ void k_cvt_feat(const float* __restrict__ x) {
    int i = blockIdx.x * 256 + threadIdx.x;          // float4 index
    if (i >= NN * DIN / 4) return;
    float4 v = reinterpret_cast<const float4*>(x)[i];
    __half2 p0 = __floats2half2_rn(v.x, v.y);
    __half2 p1 = __floats2half2_rn(v.z, v.w);
    reinterpret_cast<__half2*>(g_feat16)[2 * i]     = p0;
    reinterpret_cast<__half2*>(g_feat16)[2 * i + 1] = p1;
}

// W1 [r][k=128][n=128] -> w1T [n][r*128+k]
__global__ void k_prep_w1(const float* __restrict__ W) {
    int i = blockIdx.x * 256 + threadIdx.x;
    if (i >= RR * 128 * 128) return;
    int r = i >> 14, k = (i >> 7) & 127, n = i & 127;
    float w = W[i];
    __half h, l; split_f16(w, h, l);
    int o = n * KK + r * 128 + k;
    g_w1H[o] = h; g_w1L[o] = l;
}
// W2 [r][k=128][n=64] -> w2T [n][r*128+k]
__global__ void k_prep_w2(const float* __restrict__ W) {
    int i = blockIdx.x * 256 + threadIdx.x;
    if (i >= RR * 128 * 64) return;
    int r = i / 8192, k = (i >> 6) & 127, n = i & 63;
    float w = W[i];
    __half h, l; split_f16(w, h, l);
    int o = n * KK + r * 128 + k;
    g_w2H[o] = h; g_w2L[o] = l;
}

// ==================== degree / CSR build ====================
__global__ void k_zero() {
    int i = blockIdx.x * 256 + threadIdx.x;
    if (i < SCAN_N) { g_deg[i] = 0; g_cur[i] = 0; }
}
__global__ void k_count(const int* __restrict__ edges) {
    int i = blockIdx.x * 256 + threadIdx.x;
    if (i >= RR * EE) return;
    int r = i / EE, e = i - r * EE;
    int dst = edges[r * 2 * EE + EE + e];
    atomicAdd(&g_deg[r * NN + dst], 1);
}
__global__ __launch_bounds__(256) void k_scan1() {
    __shared__ int wsum[8];
    const int b = blockIdx.x, t = threadIdx.x;
    const int base = b * CHUNK + t * 8;
    int v[8]; int s = 0;
#pragma unroll
    for (int i = 0; i < 8; ++i) {
        int idx = base + i;
        int x = (idx < SCAN_N) ? g_deg[idx] : 0;
        v[i] = s; s += x;
    }
    const int lane = t & 31, w = t >> 5;
    int x = s;
#pragma unroll
    for (int o = 1; o < 32; o <<= 1) {
        int n = __shfl_up_sync(~0u, x, o);
        if (lane >= o) x += n;
    }
    if (lane == 31) wsum[w] = x;
    __syncthreads();
    if (t == 0) {
        int acc = 0;
#pragma unroll
        for (int i = 0; i < 8; ++i) { int tmp = wsum[i]; wsum[i] = acc; acc += tmp; }
        g_bsum[b] = acc;
    }
    __syncthreads();
    const int toff = wsum[w] + (x - s);
#pragma unroll
    for (int i = 0; i < 8; ++i) {
        int idx = base + i;
        if (idx < SCAN_N) g_off[idx] = toff + v[i];
    }
}
__global__ void k_scan2() {
    __shared__ int ws[4];
    const int t = threadIdx.x;
    const int v = (t < NBLK) ? g_bsum[t] : 0;
    const int lane = t & 31, w = t >> 5;
    int x = v;
#pragma unroll
    for (int o = 1; o < 32; o <<= 1) {
        int n = __shfl_up_sync(~0u, x, o);
        if (lane >= o) x += n;
    }
    if (lane == 31) ws[w] = x;
    __syncthreads();
    if (t == 0) {
        int acc = 0;
#pragma unroll
        for (int i = 0; i < 4; ++i) { int tmp = ws[i]; ws[i] = acc; acc += tmp; }
    }
    __syncthreads();
    if (t < NBLK) g_bsum[t] = (x - v) + ws[w];
}
__global__ void k_scan3() {
    int i = blockIdx.x * 256 + threadIdx.x;
    if (i < SCAN_N) g_off[i] += g_bsum[i >> 11];
}
__global__ void k_bin(const int* __restrict__ edges) {
    int i = blockIdx.x * 256 + threadIdx.x;
    if (i >= RR * EE) return;
    int r = i / EE, e = i - r * EE;
    const int* eb = edges + r * 2 * EE;
    int src = eb[e];
    int dst = eb[EE + e];
    int idx = r * NN + dst;
    int pos = g_off[idx] + atomicAdd(&g_cur[idx], 1);
    g_esrc[pos] = src;
}

// ==================== aggregate-first gather (mean of fp16 F rows) ==========
// Per node, per etype: Z_r = mean over in-edges of F[src] (128 fp16, fp32
// accum), rounded fp16, stored concat Z[node][r*128+c]. Writes g_gate mask.
__global__ __launch_bounds__(256)
void k_aggZ(const __half* __restrict__ F, __half* __restrict__ Z) {
    const int gw = (blockIdx.x * 256 + threadIdx.x) >> 5;
    if (gw >= NN) return;
    const int lane = threadIdx.x & 31;
    unsigned mask = 0;
#pragma unroll
    for (int r = 0; r < RR; ++r) {
        const int idx = r * NN + gw;
        const int deg = g_deg[idx];
        float4 s = make_float4(0.f, 0.f, 0.f, 0.f);
        if (deg > 0) {
            mask |= 1u << r;
            const int beg = g_off[idx];
            for (int bse = 0; bse < deg; bse += 32) {
                const int my = bse + lane;
                const int src_l = (my < deg) ? g_esrc[beg + my] : 0;
                const int n = min(32, deg - bse);
                for (int j = 0; j < n; ++j) {
                    const int src = __shfl_sync(~0u, src_l, j);
                    const uint2 u = *reinterpret_cast<const uint2*>(
                        F + (size_t)src * 128 + lane * 4);
                    const __half2 h0 = *reinterpret_cast<const __half2*>(&u.x);
                    const __half2 h1 = *reinterpret_cast<const __half2*>(&u.y);
                    const float2 f0 = __half22float2(h0);
                    const float2 f1 = __half22float2(h1);
                    s.x += f0.x; s.y += f0.y; s.z += f1.x; s.w += f1.y;
                }
            }
            const float d = 1.0f / (float)deg;
            s.x *= d; s.y *= d; s.z *= d; s.w *= d;
        }
        __half2 p0 = __floats2half2_rn(s.x, s.y);
        __half2 p1 = __floats2half2_rn(s.z, s.w);
        const size_t o2 = ((size_t)gw * KK + r * 128 + lane * 4) >> 1;  // half2 idx
        reinterpret_cast<__half2*>(Z)[o2]     = p0;
        reinterpret_cast<__half2*>(Z)[o2 + 1] = p1;
    }
    if (lane == 0) g_gate[gw] = (unsigned char)mask;
}

// ==================== fp16x2 GEMM, K=512, fused epilogue ====================
// C = A @ (Bh+Bl)^T (+ gated bias) (+relu). A [N][512] fp16; B [NB][512] hi/lo.
// CTA: 256 thr = 8 warps, tile 128m x NB n; K streamed in 4 chunks of 128.
// Warp grid 2m x 4n: warp = 64m x NB/4 n; mt=4 m16 tiles; NT = NB/64 jt-steps.
// HALF_OUT: store fp16 (layer-1 h) else fp32 (final out).
template <int ROWS>
__device__ __forceinline__ void load_tile512(char* dst, const __half* __restrict__ src,
                                             int valid_rows, int tid) {
#pragma unroll
    for (int i = 0; i < ROWS * 16 / 256; ++i) {
        const int j = i * 256 + tid;
        const int row = j >> 4;
        const int c16 = j & 15;
        uint4 v = make_uint4(0u, 0u, 0u, 0u);
        if (row < valid_rows)
            v = *reinterpret_cast<const uint4*>(src + (size_t)row * KK + c16 * 8);
        *reinterpret_cast<uint4*>(dst + row * ROWB + c16 * 16) = v;
    }
}

template <int NB, bool RELU, bool HALF_OUT>
__global__ __launch_bounds__(256, 2)
void k_mma(const __half* __restrict__ A,
           const __half* __restrict__ BH, const __half* __restrict__ BL,
           const float* __restrict__ bias,      // [RR][NB]
           void* __restrict__ Cv)               // [N][NB] fp16 or fp32
{
    constexpr int NT = NB / 64;
    extern __shared__ __align__(16) char smem[];
    char* sA  = smem;
    char* sBh = sA + 128 * ROWB;
    char* sBl = sBh + NB * ROWB;
    float* bs = reinterpret_cast<float*>(sBl + NB * ROWB);  // [RR*NB]

    const int tid  = threadIdx.x;
    const int lane = tid & 31;
    const int wid  = tid >> 5;
    const int m0   = blockIdx.x * 128;
    const int validA = (NN - m0) < 128 ? (NN - m0) : 128;

#pragma unroll
    for (int i = tid; i < RR * NB; i += 256) bs[i] = bias[i];

    const int wm = (wid >> 2) * 64;          // warp m offset (2 groups of 64)
    const int wn = (wid & 3) * (NB / 4);     // warp n offset (4 groups)
    const int aoff = (lane & 15) * ROWB + (lane >> 4) * 16;
    const int boff = ((lane & 7) + ((lane >> 4) << 3)) * ROWB + ((lane >> 3) & 1) * 16;

    const uint32_t uA  = smem_to_u32(sA);
    const uint32_t uBh = smem_to_u32(sBh);
    const uint32_t uBl = smem_to_u32(sBl);

    float acc[4][NT * 2][4];
#pragma unroll
    for (int mt = 0; mt < 4; ++mt)
#pragma unroll
        for (int nt = 0; nt < NT * 2; ++nt)
#pragma unroll
            for (int q = 0; q < 4; ++q) acc[mt][nt][q] = 0.f;

    for (int kc = 0; kc < 4; ++kc) {
        if (kc) __syncthreads();
        load_tile512<128>(sA, A + (size_t)m0 * KK + kc * 128, validA, tid);
        load_tile512<NB>(sBh, BH + kc * 128, NB, tid);
        load_tile512<NB>(sBl, BL + kc * 128, NB, tid);
        __syncthreads();

#pragma unroll
        for (int ks = 0; ks < 8; ++ks) {
            const int kb = ks * 32;
            uint32_t a[4][4];
#pragma unroll
            for (int mt = 0; mt < 4; ++mt) {
                const uint32_t base = (wm + mt * 16) * ROWB + aoff + kb;
                LDSM_X4(a[mt][0], a[mt][1], a[mt][2], a[mt][3], uA + base);
            }
#pragma unroll
            for (int jt = 0; jt < NT; ++jt) {
                const uint32_t bbase = (wn + jt * 16) * ROWB + boff + kb;
                uint32_t bh[4], bl[4];
                LDSM_X4(bh[0], bh[1], bh[2], bh[3], uBh + bbase);
                LDSM_X4(bl[0], bl[1], bl[2], bl[3], uBl + bbase);
#pragma unroll
                for (int mt = 0; mt < 4; ++mt) {
                    MMA_F16(acc[mt][2 * jt],     a[mt], bh[0], bh[1]);
                    MMA_F16(acc[mt][2 * jt + 1], a[mt], bh[2], bh[3]);
                    MMA_F16(acc[mt][2 * jt],     a[mt], bl[0], bl[1]);
                    MMA_F16(acc[mt][2 * jt + 1], a[mt], bl[2], bl[3]);
                }
            }
        }
    }

    // fused epilogue: + gated bias, optional relu, direct store (fp16 or fp32)
#pragma unroll
    for (int mt = 0; mt < 4; ++mt) {
        const int rbase = m0 + wm + mt * 16 + (lane >> 2);
#pragma unroll
        for (int half = 0; half < 2; ++half) {
            const int row = rbase + half * 8;
            if (row >= NN) continue;
            const unsigned g = g_gate[row];
#pragma unroll
            for (int nt = 0; nt < NT * 2; ++nt) {
                const int col = wn + nt * 8 + (lane & 3) * 2;
                float bx = 0.f, by = 0.f;
#pragma unroll
                for (int r = 0; r < RR; ++r) {
                    if ((g >> r) & 1) {
                        bx += bs[r * NB + col];
                        by += bs[r * NB + col + 1];
                    }
                }
                float x = acc[mt][nt][half * 2 + 0] + bx;
                float y = acc[mt][nt][half * 2 + 1] + by;
                if (RELU) { x = fmaxf(x, 0.f); y = fmaxf(y, 0.f); }
                if (HALF_OUT) {
                    *reinterpret_cast<__half2*>(
                        reinterpret_cast<__half*>(Cv) + (size_t)row * NB + col) =
                        __floats2half2_rn(x, y);
                } else {
                    *reinterpret_cast<float2*>(
                        reinterpret_cast<float*>(Cv) + (size_t)row * NB + col) =
                        make_float2(x, y);
                }
            }
        }
    }
}

// ==================== launch ====================
extern "C" void kernel_launch(void* const* d_in, const int* in_sizes, int n_in,
                              void* d_out, int out_size) {
    const float* feat  = (const float*)d_in[0];
    const float* W1    = (const float*)d_in[1];
    const float* b1    = (const float*)d_in[2];
    const float* W2    = (const float*)d_in[3];
    const float* b2    = (const float*)d_in[4];
    const int*   edges = (const int*)d_in[5];
    float* out = (float*)d_out;

    void *pZ, *pF16, *pH16, *pW1H, *pW1L, *pW2H, *pW2L;
    cudaGetSymbolAddress(&pZ,   g_Z);
    cudaGetSymbolAddress(&pF16, g_feat16);
    cudaGetSymbolAddress(&pH16, g_h16);
    cudaGetSymbolAddress(&pW1H, g_w1H);
    cudaGetSymbolAddress(&pW1L, g_w1L);
    cudaGetSymbolAddress(&pW2H, g_w2H);
    cudaGetSymbolAddress(&pW2L, g_w2L);

    const int smem1 = (128 + 128 + 128) * ROWB + RR * 128 * 4;  // 106496
    const int smem2 = (128 + 64 + 64) * ROWB + RR * 64 * 4;     //  70656
    cudaFuncSetAttribute((const void*)k_mma<128, true, true>,
                         cudaFuncAttributeMaxDynamicSharedMemorySize, smem1);
    cudaFuncSetAttribute((const void*)k_mma<64, false, false>,
                         cudaFuncAttributeMaxDynamicSharedMemorySize, smem2);

    const dim3 gg((NN + 127) / 128);
    const int aggGrid = (NN * 32 + 255) / 256;

    // CSR build + conversions
    k_zero<<<(SCAN_N + 255) / 256, 256>>>();
    k_count<<<(RR * EE + 255) / 256, 256>>>(edges);
    k_cvt_feat<<<(NN * DIN / 4 + 255) / 256, 256>>>(feat);
    k_scan1<<<NBLK, 256>>>();
    k_scan2<<<1, 128>>>();
    k_scan3<<<(SCAN_N + 255) / 256, 256>>>();
    k_bin<<<(RR * EE + 255) / 256, 256>>>(edges);

    // weight prep
    k_prep_w1<<<(RR * 128 * 128 + 255) / 256, 256>>>(W1);
    k_prep_w2<<<(RR * 128 * 64 + 255) / 256, 256>>>(W2);

    // layer 1: aggregate feat16 -> Z, GEMM (K=512), bias+relu epilogue -> h16
    k_aggZ<<<aggGrid, 256>>>((const __half*)pF16, (__half*)pZ);
    k_mma<128, true, true><<<gg, 256, smem1>>>(
        (const __half*)pZ, (const __half*)pW1H, (const __half*)pW1L, b1, pH16);

    // layer 2: aggregate h16 -> Z, GEMM writes fp32 out directly
    k_aggZ<<<aggGrid, 256>>>((const __half*)pH16, (__half*)pZ);
    k_mma<64, false, false><<<gg, 256, smem2>>>(
        (const __half*)pZ, (const __half*)pW2H, (const __half*)pW2L, b2, out);
}

// round 11
// speedup vs baseline: 1.6978x; 1.2341x over previous
#include <cuda_runtime.h>
#include <cuda_fp16.h>
#include <cstdint>
#include <cstddef>

// Problem constants
#define NN   50000
#define EE   200000
#define RR   4
#define DIN  128
#define DH   128
#define DOUT 64
#define KK   512          // concat-K = RR * 128

#define SCAN_N (RR * NN)
#define CHUNK  2048
#define NBLK   ((SCAN_N + CHUNK - 1) / CHUNK)   // 98

// smem row stride for MMA tiles: 128 fp16 + pad = 272 bytes (bank-rotating)
#define ROWB 272

// setup kernel index ranges
#define CVT_N   (NN * DIN / 4)            // 1,600,000 float4s
#define PW1_N   (RR * 128 * 128)          // 65536
#define PW2_N   (RR * 128 * 64)           // 32768
#define SETUP_N (CVT_N + PW1_N + PW2_N)

// -------- scratch (static device globals) --------
__device__ __half g_Z[(size_t)NN * KK];        // agg means, fp16  [N][512]
__device__ __half g_feat16[(size_t)NN * DIN];  // feat rounded to fp16
__device__ __half g_h16[(size_t)NN * DH];      // relu(layer-1 out), fp16
__device__ __half g_w1[DH * KK];               // W1 stacked^T [128 n][512 k]
__device__ __half g_w2[DOUT * KK];             // W2 stacked^T [64 n][512 k]
__device__ unsigned char g_gate[NN];           // per-node etype gate bits
__device__ int g_deg[SCAN_N];
__device__ int g_off[SCAN_N];                  // per-chunk exclusive scan
__device__ int g_cur[SCAN_N];
__device__ int g_bsum[NBLK];                   // chunk base offsets (after scan2)
__device__ int g_esrc[RR * EE];

__device__ __forceinline__ uint32_t smem_to_u32(const void* p) {
    uint32_t a;
    asm("{ .reg .u64 t; cvta.to.shared.u64 t, %1; cvt.u32.u64 %0, t; }"
        : "=r"(a) : "l"(p));
    return a;
}

#define LDSM_X4(r0, r1, r2, r3, addr) \
    asm volatile("ldmatrix.sync.aligned.m8n8.x4.shared.b16 {%0,%1,%2,%3}, [%4];" \
                 : "=r"(r0), "=r"(r1), "=r"(r2), "=r"(r3) : "r"(addr))

#define MMA_F16(c, a, b0, b1) \
    asm volatile("mma.sync.aligned.m16n8k16.row.col.f32.f16.f16.f32 " \
                 "{%0,%1,%2,%3},{%4,%5,%6,%7},{%8,%9},{%0,%1,%2,%3};" \
                 : "+f"((c)[0]), "+f"((c)[1]), "+f"((c)[2]), "+f"((c)[3]) \
                 : "r"((a)[0]), "r"((a)[1]), "r"((a)[2]), "r"((a)[3]), \
                   "r"(b0), "r"(b1))

// ==================== fused setup: zero + cvt feat + prep W1/W2 =============
__global__ void k_setup(const float* __restrict__ feat,
                        const float* __restrict__ W1,
                        const float* __restrict__ W2) {
    const int i = blockIdx.x * 256 + threadIdx.x;
    if (i < SCAN_N) { g_deg[i] = 0; g_cur[i] = 0; }
    if (i < CVT_N) {
        float4 v = reinterpret_cast<const float4*>(feat)[i];
        reinterpret_cast<__half2*>(g_feat16)[2 * i]     = __floats2half2_rn(v.x, v.y);
        reinterpret_cast<__half2*>(g_feat16)[2 * i + 1] = __floats2half2_rn(v.z, v.w);
    } else if (i < CVT_N + PW1_N) {
        const int j = i - CVT_N;                 // W1 [r][k=128][n=128]
        const int r = j >> 14, k = (j >> 7) & 127, n = j & 127;
        g_w1[n * KK + r * 128 + k] = __float2half(W1[j]);
    } else if (i < SETUP_N) {
        const int j = i - CVT_N - PW1_N;         // W2 [r][k=128][n=64]
        const int r = j / 8192, k = (j >> 6) & 127, n = j & 63;
        g_w2[n * KK + r * 128 + k] = __float2half(W2[j]);
    }
}

// ==================== degree / CSR build ====================
__global__ void k_count(const int* __restrict__ edges) {
    int i = blockIdx.x * 256 + threadIdx.x;
    if (i >= RR * EE) return;
    int r = i / EE, e = i - r * EE;
    int dst = edges[r * 2 * EE + EE + e];
    atomicAdd(&g_deg[r * NN + dst], 1);
}
__global__ __launch_bounds__(256) void k_scan1() {
    __shared__ int wsum[8];
    const int b = blockIdx.x, t = threadIdx.x;
    const int base = b * CHUNK + t * 8;
    int v[8]; int s = 0;
#pragma unroll
    for (int i = 0; i < 8; ++i) {
        int idx = base + i;
        int x = (idx < SCAN_N) ? g_deg[idx] : 0;
        v[i] = s; s += x;
    }
    const int lane = t & 31, w = t >> 5;
    int x = s;
#pragma unroll
    for (int o = 1; o < 32; o <<= 1) {
        int n = __shfl_up_sync(~0u, x, o);
        if (lane >= o) x += n;
    }
    if (lane == 31) wsum[w] = x;
    __syncthreads();
    if (t == 0) {
        int acc = 0;
#pragma unroll
        for (int i = 0; i < 8; ++i) { int tmp = wsum[i]; wsum[i] = acc; acc += tmp; }
        g_bsum[b] = acc;
    }
    __syncthreads();
    const int toff = wsum[w] + (x - s);
#pragma unroll
    for (int i = 0; i < 8; ++i) {
        int idx = base + i;
        if (idx < SCAN_N) g_off[idx] = toff + v[i];
    }
}
__global__ void k_scan2() {
    __shared__ int ws[4];
    const int t = threadIdx.x;
    const int v = (t < NBLK) ? g_bsum[t] : 0;
    const int lane = t & 31, w = t >> 5;
    int x = v;
#pragma unroll
    for (int o = 1; o < 32; o <<= 1) {
        int n = __shfl_up_sync(~0u, x, o);
        if (lane >= o) x += n;
    }
    if (lane == 31) ws[w] = x;
    __syncthreads();
    if (t == 0) {
        int acc = 0;
#pragma unroll
        for (int i = 0; i < 4; ++i) { int tmp = ws[i]; ws[i] = acc; acc += tmp; }
    }
    __syncthreads();
    if (t < NBLK) g_bsum[t] = (x - v) + ws[w];
}
// bin with block-offset folded in (no scan3 kernel)
__global__ void k_bin(const int* __restrict__ edges) {
    int i = blockIdx.x * 256 + threadIdx.x;
    if (i >= RR * EE) return;
    int r = i / EE, e = i - r * EE;
    const int* eb = edges + r * 2 * EE;
    int src = eb[e];
    int dst = eb[EE + e];
    int idx = r * NN + dst;
    int pos = g_off[idx] + g_bsum[idx >> 11] + atomicAdd(&g_cur[idx], 1);
    g_esrc[pos] = src;
}

// ==================== aggregate-first gather (mean of fp16 F rows) ==========
__global__ __launch_bounds__(256)
void k_aggZ(const __half* __restrict__ F, __half* __restrict__ Z) {
    const int gw = (blockIdx.x * 256 + threadIdx.x) >> 5;
    if (gw >= NN) return;
    const int lane = threadIdx.x & 31;
    unsigned mask = 0;
#pragma unroll
    for (int r = 0; r < RR; ++r) {
        const int idx = r * NN + gw;
        const int deg = g_deg[idx];
        float4 s = make_float4(0.f, 0.f, 0.f, 0.f);
        if (deg > 0) {
            mask |= 1u << r;
            const int beg = g_off[idx] + g_bsum[idx >> 11];
            for (int bse = 0; bse < deg; bse += 32) {
                const int my = bse + lane;
                const int src_l = (my < deg) ? g_esrc[beg + my] : 0;
                const int n = min(32, deg - bse);
                for (int j = 0; j < n; ++j) {
                    const int src = __shfl_sync(~0u, src_l, j);
                    const uint2 u = *reinterpret_cast<const uint2*>(
                        F + (size_t)src * 128 + lane * 4);
                    const float2 f0 = __half22float2(*reinterpret_cast<const __half2*>(&u.x));
                    const float2 f1 = __half22float2(*reinterpret_cast<const __half2*>(&u.y));
                    s.x += f0.x; s.y += f0.y; s.z += f1.x; s.w += f1.y;
                }
            }
            const float d = 1.0f / (float)deg;
            s.x *= d; s.y *= d; s.z *= d; s.w *= d;
        }
        const size_t o2 = ((size_t)gw * KK + r * 128 + lane * 4) >> 1;  // half2 idx
        reinterpret_cast<__half2*>(Z)[o2]     = __floats2half2_rn(s.x, s.y);
        reinterpret_cast<__half2*>(Z)[o2 + 1] = __floats2half2_rn(s.z, s.w);
    }
    if (lane == 0) g_gate[gw] = (unsigned char)mask;
}

// ==================== fp16 GEMM (single pass), K=512, fused epilogue ========
// C = A @ B^T (+ gated bias) (+relu). A [N][512] fp16; B [NB][512] fp16.
// CTA: 256 thr = 8 warps, tile 128m x NB n; K streamed in 4 chunks of 128.
// Warp grid 2m x 4n: warp = 64m x NB/4 n; mt=4 m16 tiles; NT = NB/64 jt-steps.
template <int ROWS>
__device__ __forceinline__ void load_tile512(char* dst, const __half* __restrict__ src,
                                             int valid_rows, int tid) {
#pragma unroll
    for (int i = 0; i < ROWS * 16 / 256; ++i) {
        const int j = i * 256 + tid;
        const int row = j >> 4;
        const int c16 = j & 15;
        uint4 v = make_uint4(0u, 0u, 0u, 0u);
        if (row < valid_rows)
            v = *reinterpret_cast<const uint4*>(src + (size_t)row * KK + c16 * 8);
        *reinterpret_cast<uint4*>(dst + row * ROWB + c16 * 16) = v;
    }
}

template <int NB, bool RELU, bool HALF_OUT>
__global__ __launch_bounds__(256, 2)
void k_mma(const __half* __restrict__ A, const __half* __restrict__ B,
           const float* __restrict__ bias,      // [RR][NB]
           void* __restrict__ Cv)               // [N][NB] fp16 or fp32
{
    constexpr int NT = NB / 64;
    extern __shared__ __align__(16) char smem[];
    char* sA = smem;
    char* sB = sA + 128 * ROWB;
    float* bs = reinterpret_cast<float*>(sB + NB * ROWB);  // [RR*NB]

    const int tid  = threadIdx.x;
    const int lane = tid & 31;
    const int wid  = tid >> 5;
    const int m0   = blockIdx.x * 128;
    const int validA = (NN - m0) < 128 ? (NN - m0) : 128;

#pragma unroll
    for (int i = tid; i < RR * NB; i += 256) bs[i] = bias[i];

    const int wm = (wid >> 2) * 64;
    const int wn = (wid & 3) * (NB / 4);
    const int aoff = (lane & 15) * ROWB + (lane >> 4) * 16;
    const int boff = ((lane & 7) + ((lane >> 4) << 3)) * ROWB + ((lane >> 3) & 1) * 16;

    const uint32_t uA = smem_to_u32(sA);
    const uint32_t uB = smem_to_u32(sB);

    float acc[4][NT * 2][4];
#pragma unroll
    for (int mt = 0; mt < 4; ++mt)
#pragma unroll
        for (int nt = 0; nt < NT * 2; ++nt)
#pragma unroll
            for (int q = 0; q < 4; ++q) acc[mt][nt][q] = 0.f;

    for (int kc = 0; kc < 4; ++kc) {
        if (kc) __syncthreads();
        load_tile512<128>(sA, A + (size_t)m0 * KK + kc * 128, validA, tid);
        load_tile512<NB>(sB, B + kc * 128, NB, tid);
        __syncthreads();

#pragma unroll
        for (int ks = 0; ks < 8; ++ks) {
            const int kb = ks * 32;
            uint32_t a[4][4];
#pragma unroll
            for (int mt = 0; mt < 4; ++mt) {
                const uint32_t base = (wm + mt * 16) * ROWB + aoff + kb;
                LDSM_X4(a[mt][0], a[mt][1], a[mt][2], a[mt][3], uA + base);
            }
#pragma unroll
            for (int jt = 0; jt < NT; ++jt) {
                const uint32_t bbase = (wn + jt * 16) * ROWB + boff + kb;
                uint32_t b[4];
                LDSM_X4(b[0], b[1], b[2], b[3], uB + bbase);
#pragma unroll
                for (int mt = 0; mt < 4; ++mt) {
                    MMA_F16(acc[mt][2 * jt],     a[mt], b[0], b[1]);
                    MMA_F16(acc[mt][2 * jt + 1], a[mt], b[2], b[3]);
                }
            }
        }
    }

    // fused epilogue: + gated bias, optional relu, store fp16 or fp32
#pragma unroll
    for (int mt = 0; mt < 4; ++mt) {
        const int rbase = m0 + wm + mt * 16 + (lane >> 2);
#pragma unroll
        for (int half = 0; half < 2; ++half) {
            const int row = rbase + half * 8;
            if (row >= NN) continue;
            const unsigned g = g_gate[row];
#pragma unroll
            for (int nt = 0; nt < NT * 2; ++nt) {
                const int col = wn + nt * 8 + (lane & 3) * 2;
                float bx = 0.f, by = 0.f;
#pragma unroll
                for (int r = 0; r < RR; ++r) {
                    if ((g >> r) & 1) {
                        bx += bs[r * NB + col];
                        by += bs[r * NB + col + 1];
                    }
                }
                float x = acc[mt][nt][half * 2 + 0] + bx;
                float y = acc[mt][nt][half * 2 + 1] + by;
                if (RELU) { x = fmaxf(x, 0.f); y = fmaxf(y, 0.f); }
                if (HALF_OUT) {
                    *reinterpret_cast<__half2*>(
                        reinterpret_cast<__half*>(Cv) + (size_t)row * NB + col) =
                        __floats2half2_rn(x, y);
                } else {
                    *reinterpret_cast<float2*>(
                        reinterpret_cast<float*>(Cv) + (size_t)row * NB + col) =
                        make_float2(x, y);
                }
            }
        }
    }
}

// ==================== launch ====================
extern "C" void kernel_launch(void* const* d_in, const int* in_sizes, int n_in,
                              void* d_out, int out_size) {
    const float* feat  = (const float*)d_in[0];
    const float* W1    = (const float*)d_in[1];
    const float* b1    = (const float*)d_in[2];
    const float* W2    = (const float*)d_in[3];
    const float* b2    = (const float*)d_in[4];
    const int*   edges = (const int*)d_in[5];
    float* out = (float*)d_out;

    void *pZ, *pF16, *pH16, *pW1, *pW2;
    cudaGetSymbolAddress(&pZ,   g_Z);
    cudaGetSymbolAddress(&pF16, g_feat16);
    cudaGetSymbolAddress(&pH16, g_h16);
    cudaGetSymbolAddress(&pW1,  g_w1);
    cudaGetSymbolAddress(&pW2,  g_w2);

    const int smem1 = (128 + 128) * ROWB + RR * 128 * 4;  // 71680
    const int smem2 = (128 + 64) * ROWB + RR * 64 * 4;    // 53248
    cudaFuncSetAttribute((const void*)k_mma<128, true, true>,
                         cudaFuncAttributeMaxDynamicSharedMemorySize, smem1);
    cudaFuncSetAttribute((const void*)k_mma<64, false, false>,
                         cudaFuncAttributeMaxDynamicSharedMemorySize, smem2);

    const dim3 gg((NN + 127) / 128);
    const int aggGrid = (NN * 32 + 255) / 256;

    // 1: fused setup (zero counters, cvt feat->fp16, prep W1/W2 transposes)
    k_setup<<<(SETUP_N + 255) / 256, 256>>>(feat, W1, W2);
    // 2-5: CSR build (scan3 folded into consumers)
    k_count<<<(RR * EE + 255) / 256, 256>>>(edges);
    k_scan1<<<NBLK, 256>>>();
    k_scan2<<<1, 128>>>();
    k_bin<<<(RR * EE + 255) / 256, 256>>>(edges);

    // 6-7: layer 1
    k_aggZ<<<aggGrid, 256>>>((const __half*)pF16, (__half*)pZ);
    k_mma<128, true, true><<<gg, 256, smem1>>>(
        (const __half*)pZ, (const __half*)pW1, b1, pH16);

    // 8-9: layer 2
    k_aggZ<<<aggGrid, 256>>>((const __half*)pH16, (__half*)pZ);
    k_mma<64, false, false><<<gg, 256, smem2>>>(
        (const __half*)pZ, (const __half*)pW2, b2, out);
}